// round 10
// baseline (speedup 1.0000x reference)
#include <cuda_runtime.h>
#include <cuda_fp16.h>
#include <math.h>

// ---------------- problem constants ----------------
#define BB    32
#define NTOK  196
#define NP1   197
#define TKN   768
#define HH    12
#define ZZ    64
#define HIDN  3072
#define MROWS (BB*NP1)    // 6304
#define MENC  (BB*NTOK)   // 6272
#define BHN   (BB*HH)     // 384
#define KSTEPS 12
#define BETA_S 0.125f
#define EPS_LN 1e-5f
#define QKW   1536
#define BIGK  4608

typedef unsigned short ushort_t;

// ---------------- scratch (device globals; no allocation) ----------------
__device__ float    g_t    [MROWS*TKN];      // fp32 state
__device__ ushort_t g_g    [MROWS*TKN];      // fp16
__device__ ushort_t g_qk   [MROWS*QKW];      // fp16: q | k
__device__ ushort_t g_dqdkh[MROWS*BIGK];     // fp16: dq | dk | relu(h)
__device__ ushort_t g_P    [BHN*NP1*NP1];    // fp16 post-softmax
__device__ float    g_tmp  [MROWS*TKN];      // fp32 temp
__device__ ushort_t g_wstack [BIGK*TKN];     // fp16: [wq;wk;whop] rows
__device__ ushort_t g_wstackT[TKN*BIGK];     // fp16: transpose
__device__ ushort_t g_enct [TKN*TKN];
__device__ ushort_t g_dect [TKN*TKN];
__device__ ushort_t g_xt   [MENC*TKN];

__device__ __forceinline__ ushort_t f2h(float f) {
    return __half_as_ushort(__float2half_rn(f));
}

__device__ __forceinline__ void mma16(float c[4], const unsigned a[4], const unsigned b[2]) {
    asm volatile(
        "mma.sync.aligned.m16n8k16.row.col.f32.f16.f16.f32 "
        "{%0,%1,%2,%3}, {%4,%5,%6,%7}, {%8,%9}, {%0,%1,%2,%3};\n"
        : "+f"(c[0]), "+f"(c[1]), "+f"(c[2]), "+f"(c[3])
        : "r"(a[0]), "r"(a[1]), "r"(a[2]), "r"(a[3]), "r"(b[0]), "r"(b[1]));
}

__device__ __forceinline__ void ldsm4(unsigned r[4], unsigned addr) {
    asm volatile("ldmatrix.sync.aligned.m8n8.x4.shared.b16 {%0,%1,%2,%3}, [%4];"
        : "=r"(r[0]), "=r"(r[1]), "=r"(r[2]), "=r"(r[3]) : "r"(addr));
}

__global__ void cvt_h_k(const float* __restrict__ in, ushort_t* __restrict__ out, int n)
{
    int i = blockIdx.x * 256 + threadIdx.x;
    if (i < n) out[i] = f2h(in[i]);
}

// tiled half transpose
__global__ void trans_h_k(const ushort_t* __restrict__ in, ushort_t* __restrict__ out,
                          int R, int Cc)
{
    __shared__ ushort_t tile[32][33];
    int c0 = blockIdx.x * 32, r0 = blockIdx.y * 32;
    int x = threadIdx.x, y = threadIdx.y;
#pragma unroll
    for (int j = 0; j < 32; j += 8) {
        int r = r0 + y + j, c = c0 + x;
        tile[y + j][x] = (r < R && c < Cc) ? in[(size_t)r * Cc + c] : (ushort_t)0;
    }
    __syncthreads();
#pragma unroll
    for (int j = 0; j < 32; j += 8) {
        int r = c0 + y + j, c = r0 + x;
        if (r < Cc && c < R) out[(size_t)r * R + c] = tile[x][y + j];
    }
}

// ============ fp16 GEMM (NT): BM=256 BN=128 BK=64, 256 thr, warp 64x64, ldmatrix ============
#define STAGES 3
#define BM 256
#define BN 128
#define BKH 64
#define AS_H 72
#define A_STG_H (BM*AS_H)
#define B_STG_H (128*AS_H)
#define SMEM_GEMM_BYTES (STAGES*(A_STG_H+B_STG_H)*2)   // 165888

__device__ __forceinline__ void cp16(unsigned dst, const void* src, int sz) {
    asm volatile("cp.async.cg.shared.global [%0], [%1], 16, %2;\n"
                 :: "r"(dst), "l"(src), "r"(sz));
}
__device__ __forceinline__ void cp_commit() { asm volatile("cp.async.commit_group;\n"); }
__device__ __forceinline__ void cp_wait1()  { asm volatile("cp.async.wait_group 1;\n"); }

__device__ __forceinline__ void load_stage_h(
    const ushort_t* __restrict__ A, const ushort_t* __restrict__ B,
    int M, int K, int m0, int n0, int kt, int tid,
    unsigned sA, unsigned sB)
{
#pragma unroll
    for (int s = 0; s < 8; s++) {
        int id = tid + s * 256;
        int r = id >> 3, c8 = (id & 7) << 3;
        unsigned dst = sA + (unsigned)(r * AS_H + c8) * 2u;
        bool ok = (m0 + r < M);
        const ushort_t* src = ok ? (A + (size_t)(m0 + r) * K + kt + c8) : A;
        cp16(dst, src, ok ? 16 : 0);
    }
#pragma unroll
    for (int s = 0; s < 4; s++) {
        int id = tid + s * 256;
        int r = id >> 3, c8 = (id & 7) << 3;
        unsigned dst = sB + (unsigned)(r * AS_H + c8) * 2u;
        cp16(dst, B + (size_t)(n0 + r) * K + kt + c8, 16);
    }
}

// SPLIT: cols < QKW -> fp16 Cv (ldc QKW); cols >= QKW -> relu fp16 Cv2 (ldc BIGK)
template<bool BIAS, bool RELU, bool ACC, bool OTF, bool SPLIT>
__global__ void __launch_bounds__(256, 1) gemm_h_k(
    const ushort_t* __restrict__ A, const ushort_t* __restrict__ B,
    const float* __restrict__ bias, void* __restrict__ Cv, void* __restrict__ Cv2,
    int M, int N, int K, int ldc)
{
    extern __shared__ ushort_t smh[];
    const int tid = threadIdx.x;
    const int m0 = blockIdx.y * BM, n0 = blockIdx.x * BN;
    const int lane = tid & 31, wid = tid >> 5;
    const int wm = (wid & 3) * 64, wn = (wid >> 2) * 64;
    const int g = lane >> 2, tig = lane & 3;
    const int lrow = lane & 15, lsel = lane >> 4;           // A ldmatrix addressing
    const int brow = (lane & 7) + ((lane >> 4) << 3);       // B ldmatrix addressing
    const int bcol = ((lane >> 3) & 1) * 8;

    unsigned smem_u = (unsigned)__cvta_generic_to_shared(smh);
    unsigned sB_base = smem_u + (unsigned)(STAGES * A_STG_H) * 2u;

    float acc[4][8][4];
#pragma unroll
    for (int mi = 0; mi < 4; mi++)
#pragma unroll
        for (int ni = 0; ni < 8; ni++)
#pragma unroll
            for (int v = 0; v < 4; v++) acc[mi][ni][v] = 0.f;

    const int niter = K >> 6;

#pragma unroll
    for (int p = 0; p < STAGES - 1; p++) {
        load_stage_h(A, B, M, K, m0, n0, p * BKH, tid,
                     smem_u + (unsigned)(p * A_STG_H) * 2u,
                     sB_base + (unsigned)(p * B_STG_H) * 2u);
        cp_commit();
    }

    int stc = 0;
    for (int it = 0; it < niter; it++) {
        cp_wait1();
        __syncthreads();

        int pf = it + STAGES - 1;
        if (pf < niter) {
            int st = pf % STAGES;
            load_stage_h(A, B, M, K, m0, n0, pf * BKH, tid,
                         smem_u + (unsigned)(st * A_STG_H) * 2u,
                         sB_base + (unsigned)(st * B_STG_H) * 2u);
        }
        cp_commit();

        unsigned aBase = smem_u + (unsigned)(stc * A_STG_H) * 2u;
        unsigned bBase = sB_base + (unsigned)(stc * B_STG_H) * 2u;
        stc = (stc + 1 == STAGES) ? 0 : stc + 1;
#pragma unroll
        for (int ks = 0; ks < 4; ks++) {
            unsigned af[4][4], bf[8][2];
#pragma unroll
            for (int mi = 0; mi < 4; mi++) {
                unsigned ad = aBase +
                    (unsigned)((wm + mi * 16 + lrow) * AS_H + ks * 16 + lsel * 8) * 2u;
                ldsm4(af[mi], ad);
            }
#pragma unroll
            for (int p = 0; p < 4; p++) {
                unsigned bd = bBase +
                    (unsigned)((wn + p * 16 + brow) * AS_H + ks * 16 + bcol) * 2u;
                unsigned tm[4];
                ldsm4(tm, bd);
                bf[2 * p][0] = tm[0]; bf[2 * p][1] = tm[1];
                bf[2 * p + 1][0] = tm[2]; bf[2 * p + 1][1] = tm[3];
            }
#pragma unroll
            for (int mi = 0; mi < 4; mi++)
#pragma unroll
                for (int ni = 0; ni < 8; ni++)
                    mma16(acc[mi][ni], af[mi], bf[ni]);
        }
    }

#pragma unroll
    for (int mi = 0; mi < 4; mi++) {
#pragma unroll
        for (int half = 0; half < 2; half++) {
            int row = m0 + wm + mi * 16 + g + half * 8;
            if (row < M) {
#pragma unroll
                for (int ni = 0; ni < 8; ni++) {
                    int col = n0 + wn + ni * 8 + tig * 2;
                    float v0 = acc[mi][ni][half * 2 + 0];
                    float v1 = acc[mi][ni][half * 2 + 1];
                    if (SPLIT) {
                        if (n0 < QKW) {
                            ushort_t* crow = (ushort_t*)Cv + (size_t)row * QKW;
                            crow[col] = f2h(v0); crow[col + 1] = f2h(v1);
                        } else {
                            ushort_t* crow = (ushort_t*)Cv2 + (size_t)row * BIGK;
                            crow[col] = f2h(fmaxf(v0, 0.f));
                            crow[col + 1] = f2h(fmaxf(v1, 0.f));
                        }
                    } else {
                        if (BIAS) { v0 += bias[col]; v1 += bias[col + 1]; }
                        if (RELU) { v0 = fmaxf(v0, 0.f); v1 = fmaxf(v1, 0.f); }
                        if (OTF) {
                            ushort_t* crow = (ushort_t*)Cv + (size_t)row * ldc;
                            crow[col] = f2h(v0); crow[col + 1] = f2h(v1);
                        } else {
                            float* crow = (float*)Cv + (size_t)row * ldc;
                            if (ACC) { v0 += crow[col]; v1 += crow[col + 1]; }
                            crow[col] = v0; crow[col + 1] = v1;
                        }
                    }
                }
            }
        }
    }
}

// ---------------- LayerNorm (writes fp16) ----------------
__device__ __forceinline__ float block_sum_256(float v, float* red)
{
    int lane = threadIdx.x & 31, w = threadIdx.x >> 5;
#pragma unroll
    for (int o = 16; o; o >>= 1) v += __shfl_xor_sync(0xffffffffu, v, o);
    if (lane == 0) red[w] = v;
    __syncthreads();
    if (w == 0) {
        float r = (lane < 8) ? red[lane] : 0.f;
#pragma unroll
        for (int o = 4; o; o >>= 1) r += __shfl_xor_sync(0xffffffffu, r, o);
        if (lane == 0) red[0] = r;
    }
    __syncthreads();
    float out = red[0];
    __syncthreads();
    return out;
}

__global__ void __launch_bounds__(256) ln_kernel(
    const float* __restrict__ X, const float* __restrict__ w,
    const float* __restrict__ bvec, ushort_t* __restrict__ Y, int scalar_w)
{
    __shared__ float red[32];
    int row = blockIdx.x;
    const float* x = X + (size_t)row * TKN;
    ushort_t* y = Y + (size_t)row * TKN;
    int tid = threadIdx.x;
    float v[3];
    float s = 0.f, ss = 0.f;
#pragma unroll
    for (int i = 0; i < 3; i++) {
        float t = x[tid + i * 256];
        v[i] = t; s += t; ss += t * t;
    }
    float sum  = block_sum_256(s, red);
    float sum2 = block_sum_256(ss, red);
    float mu = sum * (1.f / TKN);
    float var = sum2 * (1.f / TKN) - mu * mu;
    float r = rsqrtf(var + EPS_LN);
#pragma unroll
    for (int i = 0; i < 3; i++) {
        int c = tid + i * 256;
        float gv = (v[i] - mu) * r;
        float wv = scalar_w ? w[0] : w[c];
        y[c] = f2h(gv * wv + bvec[c]);
    }
}

// ---------------- assemble t = [cls ; enc] + pos ----------------
__global__ void assemble_t_k(const float* __restrict__ enc,
                             const float* __restrict__ cls,
                             const float* __restrict__ pos)
{
    int idx = blockIdx.x * 256 + threadIdx.x;
    if (idx >= MROWS * TKN) return;
    int d = idx % TKN;
    int row = idx / TKN;
    int b = row / NP1, n = row % NP1;
    float v;
    if (n == 0) v = cls[d];
    else        v = enc[((size_t)(b * NTOK + n - 1)) * TKN + d];
    g_t[idx] = v + pos[n * TKN + d];
}

// ---------------- fused scores + softmax ----------------
#define SC_STRIDE 264
#define SS_SMEM (2*64*AS_H*2 + 64*SC_STRIDE*4)   // 86016
__global__ void __launch_bounds__(256) attn_score_softmax_k(
    const ushort_t* __restrict__ QK, ushort_t* __restrict__ P)
{
    extern __shared__ ushort_t ssm[];
    ushort_t* Qs = ssm;
    ushort_t* Ks = ssm + 64 * AS_H;
    float*    Sc = (float*)(ssm + 2 * 64 * AS_H);

    int bh = blockIdx.y, b = bh / HH, h = bh % HH;
    int q0 = blockIdx.x * 64;
    const ushort_t* Qb = QK + (size_t)b * NP1 * QKW + h * ZZ;
    const ushort_t* Kb = Qb + TKN;
    int tid = threadIdx.x;
    int lane = tid & 31, wid = tid >> 5;
    int wm = (wid & 3) * 16, wn = (wid >> 2) * 32;
    int g = lane >> 2, tig = lane & 3;

#pragma unroll
    for (int s = 0; s < 2; s++) {
        int id = tid + s * 256;
        int r = id >> 3, c8 = (id & 7) << 3;
        uint4 qv = (q0 + r < NP1) ? *(const uint4*)(Qb + (size_t)(q0 + r) * QKW + c8)
                                  : make_uint4(0u, 0u, 0u, 0u);
        *(uint4*)&Qs[r * AS_H + c8] = qv;
    }

    for (int kt = 0; kt < 4; kt++) {
        int k0 = kt * 64;
        __syncthreads();
#pragma unroll
        for (int s = 0; s < 2; s++) {
            int id = tid + s * 256;
            int r = id >> 3, c8 = (id & 7) << 3;
            uint4 kv = (k0 + r < NP1) ? *(const uint4*)(Kb + (size_t)(k0 + r) * QKW + c8)
                                      : make_uint4(0u, 0u, 0u, 0u);
            *(uint4*)&Ks[r * AS_H + c8] = kv;
        }
        __syncthreads();

        const unsigned* Qw = (const unsigned*)Qs;
        const unsigned* Kw = (const unsigned*)Ks;
        float acc[4][4];
#pragma unroll
        for (int ni = 0; ni < 4; ni++)
#pragma unroll
            for (int v = 0; v < 4; v++) acc[ni][v] = 0.f;
#pragma unroll
        for (int ks = 0; ks < 4; ks++) {
            unsigned af[4], bf[4][2];
            const unsigned* pa = Qw + (wm + g) * 36 + ks * 8 + tig;
            af[0] = pa[0]; af[1] = pa[8 * 36]; af[2] = pa[4]; af[3] = pa[8 * 36 + 4];
#pragma unroll
            for (int ni = 0; ni < 4; ni++) {
                const unsigned* pb = Kw + (wn + ni * 8 + g) * 36 + ks * 8 + tig;
                bf[ni][0] = pb[0]; bf[ni][1] = pb[4];
            }
#pragma unroll
            for (int ni = 0; ni < 4; ni++)
                mma16(acc[ni], af, bf[ni]);
        }
#pragma unroll
        for (int half = 0; half < 2; half++) {
            int row = wm + g + half * 8;
#pragma unroll
            for (int ni = 0; ni < 4; ni++) {
                int col = k0 + wn + ni * 8 + tig * 2;
                Sc[row * SC_STRIDE + col]     = acc[ni][half * 2 + 0];
                Sc[row * SC_STRIDE + col + 1] = acc[ni][half * 2 + 1];
            }
        }
    }
    __syncthreads();

    ushort_t* Pp = P + (size_t)bh * NP1 * NP1;
#pragma unroll
    for (int rr = 0; rr < 8; rr++) {
        int row = wid * 8 + rr;
        int grow = q0 + row;
        if (grow >= NP1) continue;
        float vals[7];
        float m = -1e30f;
#pragma unroll
        for (int i = 0; i < 7; i++) {
            int c = lane + i * 32;
            float v = (c < NP1) ? BETA_S * Sc[row * SC_STRIDE + c] : -1e30f;
            vals[i] = v;
            m = fmaxf(m, v);
        }
#pragma unroll
        for (int o = 16; o; o >>= 1) m = fmaxf(m, __shfl_xor_sync(0xffffffffu, m, o));
        float s = 0.f;
#pragma unroll
        for (int i = 0; i < 7; i++) {
            int c = lane + i * 32;
            float e = (c < NP1) ? expf(vals[i] - m) : 0.f;
            vals[i] = e; s += e;
        }
#pragma unroll
        for (int o = 16; o; o >>= 1) s += __shfl_xor_sync(0xffffffffu, s, o);
        float inv = 1.f / s;
        ushort_t* prow = Pp + (size_t)grow * NP1;
#pragma unroll
        for (int i = 0; i < 7; i++) {
            int c = lane + i * 32;
            if (c < NP1) prow[c] = f2h(vals[i] * inv);
        }
    }
}

// ---------------- attention PV via fp16 mma (z=0: dq=P@K, z=1: dk=P^T@Q) ----------------
__global__ void __launch_bounds__(128) attn_av_mma_k(
    const ushort_t* __restrict__ Pb, const ushort_t* __restrict__ QK,
    ushort_t* __restrict__ OutB)
{
    __shared__ ushort_t Ps[64 * 40];
    __shared__ ushort_t Vt[64 * 40];
    const int transp = blockIdx.z;
    int bh = blockIdx.y, b = bh / HH, h = bh % HH;
    const ushort_t* Pp = Pb + (size_t)bh * NP1 * NP1;
    int v_off = transp ? 0 : TKN;
    int o_off = transp ? TKN : 0;
    const ushort_t* Vb = QK + (size_t)b * NP1 * QKW + v_off + h * ZZ;
    ushort_t* Ob = OutB + (size_t)b * NP1 * BIGK + o_off + h * ZZ;
    int m0 = blockIdx.x * 64;
    int tid = threadIdx.x, lane = tid & 31, wid = tid >> 5;
    int g = lane >> 2, tig = lane & 3, wm = wid * 16;
    float acc[8][4];
#pragma unroll
    for (int ni = 0; ni < 8; ni++)
#pragma unroll
        for (int v = 0; v < 4; v++) acc[ni][v] = 0.f;

    for (int kb = 0; kb < NP1; kb += 32) {
        __syncthreads();
#pragma unroll
        for (int s = 0; s < 16; s++) {
            int id = tid + s * 128;
            int r, kk;
            if (!transp) { r = id >> 5; kk = id & 31; }
            else         { r = id & 63; kk = id >> 6; }
            ushort_t v = 0;
            int mg = m0 + r, kg = kb + kk;
            if (mg < NP1 && kg < NP1)
                v = transp ? Pp[(size_t)kg * NP1 + mg] : Pp[(size_t)mg * NP1 + kg];
            Ps[r * 40 + kk] = v;
        }
#pragma unroll
        for (int s = 0; s < 2; s++) {
            int id = tid + s * 128;
            int r = id >> 3, c8 = (id & 7) << 3;
            uint4 v = (kb + r < NP1) ? *(const uint4*)(Vb + (size_t)(kb + r) * QKW + c8)
                                     : make_uint4(0u, 0u, 0u, 0u);
            ushort_t hv[8];
            *(uint4*)hv = v;
#pragma unroll
            for (int j = 0; j < 8; j++) Vt[(c8 + j) * 40 + r] = hv[j];
        }
        __syncthreads();
        const unsigned* Pw = (const unsigned*)Ps;
        const unsigned* Vw = (const unsigned*)Vt;
#pragma unroll
        for (int ks = 0; ks < 2; ks++) {
            unsigned af[4], bf[8][2];
            const unsigned* pa = Pw + (wm + g) * 20 + ks * 8 + tig;
            af[0] = pa[0]; af[1] = pa[8 * 20]; af[2] = pa[4]; af[3] = pa[8 * 20 + 4];
#pragma unroll
            for (int ni = 0; ni < 8; ni++) {
                const unsigned* pb = Vw + (ni * 8 + g) * 20 + ks * 8 + tig;
                bf[ni][0] = pb[0]; bf[ni][1] = pb[4];
            }
#pragma unroll
            for (int ni = 0; ni < 8; ni++)
                mma16(acc[ni], af, bf[ni]);
        }
    }
#pragma unroll
    for (int half = 0; half < 2; half++) {
        int row = m0 + wm + g + half * 8;
        if (row < NP1) {
            ushort_t* orow = Ob + (size_t)row * BIGK;
#pragma unroll
            for (int ni = 0; ni < 8; ni++) {
                int col = ni * 8 + tig * 2;
                orow[col]     = f2h(acc[ni][half * 2]);
                orow[col + 1] = f2h(acc[ni][half * 2 + 1]);
            }
        }
    }
}

// ---------------- final copy (drop cls row) ----------------
__global__ void copy_out_k(const float* __restrict__ Y, float* __restrict__ out)
{
    int idx = blockIdx.x * 256 + threadIdx.x;
    if (idx >= BB * NTOK * TKN) return;
    int d = idx % TKN;
    int r = idx / TKN;
    int b = r / NTOK, j = r % NTOK;
    out[idx] = Y[((size_t)(b * NP1 + j + 1)) * TKN + d];
}

// ---------------- driver ----------------
extern "C" void kernel_launch(void* const* d_in, const int* in_sizes, int n_in,
                              void* d_out, int out_size)
{
    const float* x      = (const float*)d_in[0];
    const float* w_enc  = (const float*)d_in[1];
    const float* b_enc  = (const float*)d_in[2];
    const float* cls    = (const float*)d_in[3];
    const float* pos    = (const float*)d_in[4];
    const float* eln_g  = (const float*)d_in[5];
    const float* eln_b  = (const float*)d_in[6];
    const float* wq     = (const float*)d_in[7];
    const float* wk     = (const float*)d_in[8];
    const float* w_hop  = (const float*)d_in[9];
    const float* dec_w  = (const float*)d_in[10];
    const float* dec_b  = (const float*)d_in[11];
    const float* w_dec  = (const float*)d_in[12];
    const float* b_dec  = (const float*)d_in[13];
    float* out = (float*)d_out;

    float *t_, *tmp_;
    ushort_t *g_, *qk_, *dqdkh_, *P_, *wstack_, *wstackT_, *enct_, *dect_, *xt_;
    cudaGetSymbolAddress((void**)&t_,      g_t);
    cudaGetSymbolAddress((void**)&g_,      g_g);
    cudaGetSymbolAddress((void**)&qk_,     g_qk);
    cudaGetSymbolAddress((void**)&dqdkh_,  g_dqdkh);
    cudaGetSymbolAddress((void**)&P_,      g_P);
    cudaGetSymbolAddress((void**)&tmp_,    g_tmp);
    cudaGetSymbolAddress((void**)&wstack_, g_wstack);
    cudaGetSymbolAddress((void**)&wstackT_,g_wstackT);
    cudaGetSymbolAddress((void**)&enct_,   g_enct);
    cudaGetSymbolAddress((void**)&dect_,   g_dect);
    cudaGetSymbolAddress((void**)&xt_,     g_xt);

    cudaFuncSetAttribute((const void*)gemm_h_k<true,  false, false, false, false>,
                         cudaFuncAttributeMaxDynamicSharedMemorySize, SMEM_GEMM_BYTES);
    cudaFuncSetAttribute((const void*)gemm_h_k<false, false, false, false, true>,
                         cudaFuncAttributeMaxDynamicSharedMemorySize, SMEM_GEMM_BYTES);
    cudaFuncSetAttribute((const void*)gemm_h_k<false, false, true,  false, false>,
                         cudaFuncAttributeMaxDynamicSharedMemorySize, SMEM_GEMM_BYTES);
    cudaFuncSetAttribute((const void*)attn_score_softmax_k,
                         cudaFuncAttributeMaxDynamicSharedMemorySize, SS_SMEM);

    const dim3 blk(256);
    const int  mtiles = (MROWS + BM - 1) / BM;     // 25
    const dim3 gridFused(BIGK / BN, mtiles);       // (36, 25)
    const dim3 gridMega(TKN / BN, mtiles);         // (6, 25)
    const dim3 gridEnc(TKN / BN, (MENC + BM - 1) / BM);

    // one-time fp16 conversions
    cvt_h_k<<<(TKN*TKN + 255) / 256, blk>>>(wq,    wstack_,              TKN*TKN);
    cvt_h_k<<<(TKN*TKN + 255) / 256, blk>>>(wk,    wstack_ + TKN*TKN,    TKN*TKN);
    cvt_h_k<<<(HIDN*TKN + 255) / 256, blk>>>(w_hop, wstack_ + 2*TKN*TKN, HIDN*TKN);
    cvt_h_k<<<(TKN*TKN + 255) / 256, blk>>>(w_enc, enct_, TKN*TKN);
    cvt_h_k<<<(TKN*TKN + 255) / 256, blk>>>(w_dec, dect_, TKN*TKN);
    cvt_h_k<<<(MENC*TKN + 255) / 256, blk>>>(x,     xt_,   MENC*TKN);
    trans_h_k<<<dim3((TKN + 31) / 32, (BIGK + 31) / 32), dim3(32, 8)>>>(
        wstack_, wstackT_, BIGK, TKN);

    // encode + assemble
    gemm_h_k<true, false, false, false, false><<<gridEnc, blk, SMEM_GEMM_BYTES>>>(
        xt_, enct_, b_enc, tmp_, nullptr, MENC, TKN, TKN, TKN);
    assemble_t_k<<<(MROWS * TKN + 255) / 256, blk>>>(tmp_, cls, pos);

    for (int s = 0; s < KSTEPS; s++) {
        ln_kernel<<<MROWS, blk>>>(t_, eln_g, eln_b, g_, 1);
        // fused projections: [q|k] -> qk ; relu(h) -> dqdkh cols 1536+
        gemm_h_k<false, false, false, false, true><<<gridFused, blk, SMEM_GEMM_BYTES>>>(
            g_, wstack_, nullptr, qk_, dqdkh_, MROWS, BIGK, TKN, 0);
        attn_score_softmax_k<<<dim3(4, BHN), blk, SS_SMEM>>>(qk_, P_);
        attn_av_mma_k<<<dim3(4, BHN, 2), dim3(128)>>>(P_, qk_, dqdkh_);
        // mega accumulate: t += [dq|dk|relu(h)] @ wstackT^T
        gemm_h_k<false, false, true, false, false><<<gridMega, blk, SMEM_GEMM_BYTES>>>(
            dqdkh_, wstackT_, nullptr, t_, nullptr, MROWS, TKN, BIGK, TKN);
    }

    ln_kernel<<<MROWS, blk>>>(t_, dec_w, dec_b, g_, 0);
    gemm_h_k<true, false, false, false, false><<<gridMega, blk, SMEM_GEMM_BYTES>>>(
        g_, dect_, b_dec, tmp_, nullptr, MROWS, TKN, TKN, TKN);
    copy_out_k<<<(BB * NTOK * TKN + 255) / 256, blk>>>(tmp_, out);
}

// round 11
// speedup vs baseline: 1.2132x; 1.2132x over previous
#include <cuda_runtime.h>
#include <cuda_fp16.h>
#include <math.h>

// ---------------- problem constants ----------------
#define BB    32
#define NTOK  196
#define NP1   197
#define TKN   768
#define HH    12
#define ZZ    64
#define HIDN  3072
#define MROWS (BB*NP1)    // 6304
#define MENC  (BB*NTOK)   // 6272
#define BHN   (BB*HH)     // 384
#define KSTEPS 12
#define BETA_S 0.125f
#define EPS_LN 1e-5f
#define QKW   1536
#define BIGK  4608

typedef unsigned short ushort_t;

// ---------------- scratch (device globals; no allocation) ----------------
__device__ float    g_t    [MROWS*TKN];      // fp32 state
__device__ ushort_t g_g    [MROWS*TKN];      // fp16
__device__ ushort_t g_qk   [MROWS*QKW];      // fp16: q | k
__device__ ushort_t g_dqdkh[MROWS*BIGK];     // fp16: dq | dk | relu(h)
__device__ ushort_t g_P    [BHN*NP1*NP1];    // fp16 post-softmax
__device__ float    g_tmp  [MROWS*TKN];      // fp32 temp
__device__ ushort_t g_wstack [BIGK*TKN];     // fp16: [wq;wk;whop] rows
__device__ ushort_t g_wstackT[TKN*BIGK];     // fp16: transpose
__device__ ushort_t g_enct [TKN*TKN];
__device__ ushort_t g_dect [TKN*TKN];
__device__ ushort_t g_xt   [MENC*TKN];

__device__ __forceinline__ ushort_t f2h(float f) {
    return __half_as_ushort(__float2half_rn(f));
}

__device__ __forceinline__ void mma16(float c[4], const unsigned a[4], const unsigned b[2]) {
    asm volatile(
        "mma.sync.aligned.m16n8k16.row.col.f32.f16.f16.f32 "
        "{%0,%1,%2,%3}, {%4,%5,%6,%7}, {%8,%9}, {%0,%1,%2,%3};\n"
        : "+f"(c[0]), "+f"(c[1]), "+f"(c[2]), "+f"(c[3])
        : "r"(a[0]), "r"(a[1]), "r"(a[2]), "r"(a[3]), "r"(b[0]), "r"(b[1]));
}

__global__ void cvt_h_k(const float* __restrict__ in, ushort_t* __restrict__ out, int n)
{
    int i = blockIdx.x * 256 + threadIdx.x;
    if (i < n) out[i] = f2h(in[i]);
}

// tiled half transpose: out[Cc x R] = in[R x Cc]^T
__global__ void trans_h_k(const ushort_t* __restrict__ in, ushort_t* __restrict__ out,
                          int R, int Cc)
{
    __shared__ ushort_t tile[32][33];
    int c0 = blockIdx.x * 32, r0 = blockIdx.y * 32;
    int x = threadIdx.x, y = threadIdx.y;
#pragma unroll
    for (int j = 0; j < 32; j += 8) {
        int r = r0 + y + j, c = c0 + x;
        tile[y + j][x] = (r < R && c < Cc) ? in[(size_t)r * Cc + c] : (ushort_t)0;
    }
    __syncthreads();
#pragma unroll
    for (int j = 0; j < 32; j += 8) {
        int r = c0 + y + j, c = r0 + x;
        if (r < Cc && c < R) out[(size_t)r * R + c] = tile[x][y + j];
    }
}

// ============ fp16 GEMM (NT): BM=256 BN=128 BK=64, 256 thr, warp 64x64 ============
#define STAGES 3
#define BM 256
#define BN 128
#define BKH 64
#define AS_H 72                     // halfs per row (stride); 36 words
#define A_STG_H (BM*AS_H)           // 18432 halfs
#define B_STG_H (128*AS_H)          // 9216 halfs
#define SMEM_GEMM_BYTES (STAGES*(A_STG_H+B_STG_H)*2)   // 165888

__device__ __forceinline__ void cp16(unsigned dst, const void* src, int sz) {
    asm volatile("cp.async.cg.shared.global [%0], [%1], 16, %2;\n"
                 :: "r"(dst), "l"(src), "r"(sz));
}
__device__ __forceinline__ void cp_commit() { asm volatile("cp.async.commit_group;\n"); }
__device__ __forceinline__ void cp_wait1()  { asm volatile("cp.async.wait_group 1;\n"); }

__device__ __forceinline__ void load_stage_h(
    const ushort_t* __restrict__ A, const ushort_t* __restrict__ B,
    int M, int K, int m0, int n0, int kt, int tid,
    unsigned sA, unsigned sB)
{
#pragma unroll
    for (int s = 0; s < 8; s++) {
        int id = tid + s * 256;
        int r = id >> 3, c8 = (id & 7) << 3;
        unsigned dst = sA + (unsigned)(r * AS_H + c8) * 2u;
        bool ok = (m0 + r < M);
        const ushort_t* src = ok ? (A + (size_t)(m0 + r) * K + kt + c8) : A;
        cp16(dst, src, ok ? 16 : 0);
    }
#pragma unroll
    for (int s = 0; s < 4; s++) {
        int id = tid + s * 256;
        int r = id >> 3, c8 = (id & 7) << 3;
        unsigned dst = sB + (unsigned)(r * AS_H + c8) * 2u;
        cp16(dst, B + (size_t)(n0 + r) * K + kt + c8, 16);
    }
}

// SPLIT: cols < QKW -> fp16 Cv (ldc QKW); cols >= QKW -> relu fp16 Cv2 (ldc BIGK)
template<bool BIAS, bool RELU, bool ACC, bool OTF, bool SPLIT>
__global__ void __launch_bounds__(256, 1) gemm_h_k(
    const ushort_t* __restrict__ A, const ushort_t* __restrict__ B,
    const float* __restrict__ bias, void* __restrict__ Cv, void* __restrict__ Cv2,
    int M, int N, int K, int ldc)
{
    extern __shared__ ushort_t smh[];
    const int tid = threadIdx.x;
    const int m0 = blockIdx.y * BM, n0 = blockIdx.x * BN;
    const int lane = tid & 31, wid = tid >> 5;
    const int wm = (wid & 3) * 64, wn = (wid >> 2) * 64;
    const int g = lane >> 2, tig = lane & 3;

    unsigned smem_u = (unsigned)__cvta_generic_to_shared(smh);
    unsigned sB_base = smem_u + (unsigned)(STAGES * A_STG_H) * 2u;

    float acc[4][8][4];
#pragma unroll
    for (int mi = 0; mi < 4; mi++)
#pragma unroll
        for (int ni = 0; ni < 8; ni++)
#pragma unroll
            for (int v = 0; v < 4; v++) acc[mi][ni][v] = 0.f;

    const int niter = K >> 6;

#pragma unroll
    for (int p = 0; p < STAGES - 1; p++) {
        load_stage_h(A, B, M, K, m0, n0, p * BKH, tid,
                     smem_u + (unsigned)(p * A_STG_H) * 2u,
                     sB_base + (unsigned)(p * B_STG_H) * 2u);
        cp_commit();
    }

    int stc = 0;
    for (int it = 0; it < niter; it++) {
        cp_wait1();
        __syncthreads();

        int pf = it + STAGES - 1;
        if (pf < niter) {
            int st = pf % STAGES;
            load_stage_h(A, B, M, K, m0, n0, pf * BKH, tid,
                         smem_u + (unsigned)(st * A_STG_H) * 2u,
                         sB_base + (unsigned)(st * B_STG_H) * 2u);
        }
        cp_commit();

        const unsigned* Aw = (const unsigned*)(smh + stc * A_STG_H);
        const unsigned* Bw = (const unsigned*)(smh + STAGES * A_STG_H + stc * B_STG_H);
        stc = (stc + 1 == STAGES) ? 0 : stc + 1;
#pragma unroll
        for (int ks = 0; ks < 4; ks++) {
            unsigned af[4][4], bf[8][2];
#pragma unroll
            for (int mi = 0; mi < 4; mi++) {
                const unsigned* p0 = Aw + (wm + mi * 16 + g) * 36 + ks * 8 + tig;
                af[mi][0] = p0[0];
                af[mi][1] = p0[8 * 36];
                af[mi][2] = p0[4];
                af[mi][3] = p0[8 * 36 + 4];
            }
#pragma unroll
            for (int ni = 0; ni < 8; ni++) {
                const unsigned* p = Bw + (wn + ni * 8 + g) * 36 + ks * 8 + tig;
                bf[ni][0] = p[0];
                bf[ni][1] = p[4];
            }
#pragma unroll
            for (int mi = 0; mi < 4; mi++)
#pragma unroll
                for (int ni = 0; ni < 8; ni++)
                    mma16(acc[mi][ni], af[mi], bf[ni]);
        }
    }

#pragma unroll
    for (int mi = 0; mi < 4; mi++) {
#pragma unroll
        for (int half = 0; half < 2; half++) {
            int row = m0 + wm + mi * 16 + g + half * 8;
            if (row < M) {
#pragma unroll
                for (int ni = 0; ni < 8; ni++) {
                    int col = n0 + wn + ni * 8 + tig * 2;
                    float v0 = acc[mi][ni][half * 2 + 0];
                    float v1 = acc[mi][ni][half * 2 + 1];
                    if (SPLIT) {
                        if (n0 < QKW) {
                            ushort_t* crow = (ushort_t*)Cv + (size_t)row * QKW;
                            crow[col] = f2h(v0); crow[col + 1] = f2h(v1);
                        } else {
                            ushort_t* crow = (ushort_t*)Cv2 + (size_t)row * BIGK;
                            crow[col] = f2h(fmaxf(v0, 0.f));
                            crow[col + 1] = f2h(fmaxf(v1, 0.f));
                        }
                    } else {
                        if (BIAS) { v0 += bias[col]; v1 += bias[col + 1]; }
                        if (RELU) { v0 = fmaxf(v0, 0.f); v1 = fmaxf(v1, 0.f); }
                        if (OTF) {
                            ushort_t* crow = (ushort_t*)Cv + (size_t)row * ldc;
                            crow[col] = f2h(v0); crow[col + 1] = f2h(v1);
                        } else {
                            float* crow = (float*)Cv + (size_t)row * ldc;
                            if (ACC) { v0 += crow[col]; v1 += crow[col + 1]; }
                            crow[col] = v0; crow[col + 1] = v1;
                        }
                    }
                }
            }
        }
    }
}

// ---------------- LayerNorm (writes fp16) ----------------
__device__ __forceinline__ float block_sum_256(float v, float* red)
{
    int lane = threadIdx.x & 31, w = threadIdx.x >> 5;
#pragma unroll
    for (int o = 16; o; o >>= 1) v += __shfl_xor_sync(0xffffffffu, v, o);
    if (lane == 0) red[w] = v;
    __syncthreads();
    if (w == 0) {
        float r = (lane < 8) ? red[lane] : 0.f;
#pragma unroll
        for (int o = 4; o; o >>= 1) r += __shfl_xor_sync(0xffffffffu, r, o);
        if (lane == 0) red[0] = r;
    }
    __syncthreads();
    float out = red[0];
    __syncthreads();
    return out;
}

__global__ void __launch_bounds__(256) ln_kernel(
    const float* __restrict__ X, const float* __restrict__ w,
    const float* __restrict__ bvec, ushort_t* __restrict__ Y, int scalar_w)
{
    __shared__ float red[32];
    int row = blockIdx.x;
    const float* x = X + (size_t)row * TKN;
    ushort_t* y = Y + (size_t)row * TKN;
    int tid = threadIdx.x;
    float v[3];
    float s = 0.f, ss = 0.f;
#pragma unroll
    for (int i = 0; i < 3; i++) {
        float t = x[tid + i * 256];
        v[i] = t; s += t; ss += t * t;
    }
    float sum  = block_sum_256(s, red);
    float sum2 = block_sum_256(ss, red);
    float mu = sum * (1.f / TKN);
    float var = sum2 * (1.f / TKN) - mu * mu;
    float r = rsqrtf(var + EPS_LN);
#pragma unroll
    for (int i = 0; i < 3; i++) {
        int c = tid + i * 256;
        float gv = (v[i] - mu) * r;
        float wv = scalar_w ? w[0] : w[c];
        y[c] = f2h(gv * wv + bvec[c]);
    }
}

// ---------------- assemble t = [cls ; enc] + pos ----------------
__global__ void assemble_t_k(const float* __restrict__ enc,
                             const float* __restrict__ cls,
                             const float* __restrict__ pos)
{
    int idx = blockIdx.x * 256 + threadIdx.x;
    if (idx >= MROWS * TKN) return;
    int d = idx % TKN;
    int row = idx / TKN;
    int b = row / NP1, n = row % NP1;
    float v;
    if (n == 0) v = cls[d];
    else        v = enc[((size_t)(b * NTOK + n - 1)) * TKN + d];
    g_t[idx] = v + pos[n * TKN + d];
}

// ---------------- fused scores + softmax (fp16 in, fp16 P out) ----------------
#define SC_STRIDE 264
#define SS_SMEM (2*64*AS_H*2 + 64*SC_STRIDE*4)   // 86016
__global__ void __launch_bounds__(256) attn_score_softmax_k(
    const ushort_t* __restrict__ QK, ushort_t* __restrict__ P)
{
    extern __shared__ ushort_t ssm[];
    ushort_t* Qs = ssm;
    ushort_t* Ks = ssm + 64 * AS_H;
    float*    Sc = (float*)(ssm + 2 * 64 * AS_H);

    int bh = blockIdx.y, b = bh / HH, h = bh % HH;
    int q0 = blockIdx.x * 64;
    const ushort_t* Qb = QK + (size_t)b * NP1 * QKW + h * ZZ;
    const ushort_t* Kb = Qb + TKN;
    int tid = threadIdx.x;
    int lane = tid & 31, wid = tid >> 5;
    int wm = (wid & 3) * 16, wn = (wid >> 2) * 32;
    int g = lane >> 2, tig = lane & 3;

#pragma unroll
    for (int s = 0; s < 2; s++) {
        int id = tid + s * 256;
        int r = id >> 3, c8 = (id & 7) << 3;
        uint4 qv = (q0 + r < NP1) ? *(const uint4*)(Qb + (size_t)(q0 + r) * QKW + c8)
                                  : make_uint4(0u, 0u, 0u, 0u);
        *(uint4*)&Qs[r * AS_H + c8] = qv;
    }

    for (int kt = 0; kt < 4; kt++) {
        int k0 = kt * 64;
        __syncthreads();
#pragma unroll
        for (int s = 0; s < 2; s++) {
            int id = tid + s * 256;
            int r = id >> 3, c8 = (id & 7) << 3;
            uint4 kv = (k0 + r < NP1) ? *(const uint4*)(Kb + (size_t)(k0 + r) * QKW + c8)
                                      : make_uint4(0u, 0u, 0u, 0u);
            *(uint4*)&Ks[r * AS_H + c8] = kv;
        }
        __syncthreads();

        const unsigned* Qw = (const unsigned*)Qs;
        const unsigned* Kw = (const unsigned*)Ks;
        float acc[4][4];
#pragma unroll
        for (int ni = 0; ni < 4; ni++)
#pragma unroll
            for (int v = 0; v < 4; v++) acc[ni][v] = 0.f;
#pragma unroll
        for (int ks = 0; ks < 4; ks++) {
            unsigned af[4], bf[4][2];
            const unsigned* pa = Qw + (wm + g) * 36 + ks * 8 + tig;
            af[0] = pa[0]; af[1] = pa[8 * 36]; af[2] = pa[4]; af[3] = pa[8 * 36 + 4];
#pragma unroll
            for (int ni = 0; ni < 4; ni++) {
                const unsigned* pb = Kw + (wn + ni * 8 + g) * 36 + ks * 8 + tig;
                bf[ni][0] = pb[0]; bf[ni][1] = pb[4];
            }
#pragma unroll
            for (int ni = 0; ni < 4; ni++)
                mma16(acc[ni], af, bf[ni]);
        }
#pragma unroll
        for (int half = 0; half < 2; half++) {
            int row = wm + g + half * 8;
#pragma unroll
            for (int ni = 0; ni < 4; ni++) {
                int col = k0 + wn + ni * 8 + tig * 2;
                Sc[row * SC_STRIDE + col]     = acc[ni][half * 2 + 0];
                Sc[row * SC_STRIDE + col + 1] = acc[ni][half * 2 + 1];
            }
        }
    }
    __syncthreads();

    ushort_t* Pp = P + (size_t)bh * NP1 * NP1;
#pragma unroll
    for (int rr = 0; rr < 8; rr++) {
        int row = wid * 8 + rr;
        int grow = q0 + row;
        if (grow >= NP1) continue;
        float vals[7];
        float m = -1e30f;
#pragma unroll
        for (int i = 0; i < 7; i++) {
            int c = lane + i * 32;
            float v = (c < NP1) ? BETA_S * Sc[row * SC_STRIDE + c] : -1e30f;
            vals[i] = v;
            m = fmaxf(m, v);
        }
#pragma unroll
        for (int o = 16; o; o >>= 1) m = fmaxf(m, __shfl_xor_sync(0xffffffffu, m, o));
        float s = 0.f;
#pragma unroll
        for (int i = 0; i < 7; i++) {
            int c = lane + i * 32;
            float e = (c < NP1) ? expf(vals[i] - m) : 0.f;
            vals[i] = e; s += e;
        }
#pragma unroll
        for (int o = 16; o; o >>= 1) s += __shfl_xor_sync(0xffffffffu, s, o);
        float inv = 1.f / s;
        ushort_t* prow = Pp + (size_t)grow * NP1;
#pragma unroll
        for (int i = 0; i < 7; i++) {
            int c = lane + i * 32;
            if (c < NP1) prow[c] = f2h(vals[i] * inv);
        }
    }
}

// ---------------- attention PV via fp16 mma ----------------
// TRANSP=false: dq = P @ K ; TRANSP=true: dk = P^T @ Q.
template<bool TRANSP>
__global__ void __launch_bounds__(128) attn_av_mma_k(
    const ushort_t* __restrict__ Pb, const ushort_t* __restrict__ QK,
    ushort_t* __restrict__ OutB, int v_off, int o_off)
{
    __shared__ ushort_t Ps[64 * 40];
    __shared__ ushort_t Vt[64 * 40];   // V transposed: [z][k]
    int bh = blockIdx.y, b = bh / HH, h = bh % HH;
    const ushort_t* Pp = Pb + (size_t)bh * NP1 * NP1;
    const ushort_t* Vb = QK + (size_t)b * NP1 * QKW + v_off + h * ZZ;
    ushort_t* Ob = OutB + (size_t)b * NP1 * BIGK + o_off + h * ZZ;
    int m0 = blockIdx.x * 64;
    int tid = threadIdx.x, lane = tid & 31, wid = tid >> 5;
    int g = lane >> 2, tig = lane & 3, wm = wid * 16;
    float acc[8][4];
#pragma unroll
    for (int ni = 0; ni < 8; ni++)
#pragma unroll
        for (int v = 0; v < 4; v++) acc[ni][v] = 0.f;

    for (int kb = 0; kb < NP1; kb += 32) {
        __syncthreads();
        // stage P chunk [64 m][32 k] as fp16
#pragma unroll
        for (int s = 0; s < 16; s++) {
            int id = tid + s * 128;
            int r, kk;
            if (!TRANSP) { r = id >> 5; kk = id & 31; }
            else         { r = id & 63; kk = id >> 6; }
            ushort_t v = 0;
            int mg = m0 + r, kg = kb + kk;
            if (mg < NP1 && kg < NP1)
                v = TRANSP ? Pp[(size_t)kg * NP1 + mg] : Pp[(size_t)mg * NP1 + kg];
            Ps[r * 40 + kk] = v;
        }
        // stage V transposed: Vt[z][k] from V[kb+r][z]
#pragma unroll
        for (int s = 0; s < 2; s++) {
            int id = tid + s * 128;
            int r = id >> 3, c8 = (id & 7) << 3;
            uint4 v = (kb + r < NP1) ? *(const uint4*)(Vb + (size_t)(kb + r) * QKW + c8)
                                     : make_uint4(0u, 0u, 0u, 0u);
            ushort_t hv[8];
            *(uint4*)hv = v;
#pragma unroll
            for (int j = 0; j < 8; j++) Vt[(c8 + j) * 40 + r] = hv[j];
        }
        __syncthreads();
        const unsigned* Pw = (const unsigned*)Ps;
        const unsigned* Vw = (const unsigned*)Vt;
#pragma unroll
        for (int ks = 0; ks < 2; ks++) {
            unsigned af[4], bf[8][2];
            const unsigned* pa = Pw + (wm + g) * 20 + ks * 8 + tig;
            af[0] = pa[0]; af[1] = pa[8 * 20]; af[2] = pa[4]; af[3] = pa[8 * 20 + 4];
#pragma unroll
            for (int ni = 0; ni < 8; ni++) {
                const unsigned* pb = Vw + (ni * 8 + g) * 20 + ks * 8 + tig;
                bf[ni][0] = pb[0]; bf[ni][1] = pb[4];
            }
#pragma unroll
            for (int ni = 0; ni < 8; ni++)
                mma16(acc[ni], af, bf[ni]);
        }
    }
#pragma unroll
    for (int half = 0; half < 2; half++) {
        int row = m0 + wm + g + half * 8;
        if (row < NP1) {
            ushort_t* orow = Ob + (size_t)row * BIGK;
#pragma unroll
            for (int ni = 0; ni < 8; ni++) {
                int col = ni * 8 + tig * 2;
                orow[col]     = f2h(acc[ni][half * 2]);
                orow[col + 1] = f2h(acc[ni][half * 2 + 1]);
            }
        }
    }
}

// ---------------- final copy (drop cls row) ----------------
__global__ void copy_out_k(const float* __restrict__ Y, float* __restrict__ out)
{
    int idx = blockIdx.x * 256 + threadIdx.x;
    if (idx >= BB * NTOK * TKN) return;
    int d = idx % TKN;
    int r = idx / TKN;
    int b = r / NTOK, j = r % NTOK;
    out[idx] = Y[((size_t)(b * NP1 + j + 1)) * TKN + d];
}

// ---------------- driver ----------------
extern "C" void kernel_launch(void* const* d_in, const int* in_sizes, int n_in,
                              void* d_out, int out_size)
{
    const float* x      = (const float*)d_in[0];
    const float* w_enc  = (const float*)d_in[1];
    const float* b_enc  = (const float*)d_in[2];
    const float* cls    = (const float*)d_in[3];
    const float* pos    = (const float*)d_in[4];
    const float* eln_g  = (const float*)d_in[5];
    const float* eln_b  = (const float*)d_in[6];
    const float* wq     = (const float*)d_in[7];
    const float* wk     = (const float*)d_in[8];
    const float* w_hop  = (const float*)d_in[9];
    const float* dec_w  = (const float*)d_in[10];
    const float* dec_b  = (const float*)d_in[11];
    const float* w_dec  = (const float*)d_in[12];
    const float* b_dec  = (const float*)d_in[13];
    float* out = (float*)d_out;

    float *t_, *tmp_;
    ushort_t *g_, *qk_, *dqdkh_, *P_, *wstack_, *wstackT_, *enct_, *dect_, *xt_;
    cudaGetSymbolAddress((void**)&t_,      g_t);
    cudaGetSymbolAddress((void**)&g_,      g_g);
    cudaGetSymbolAddress((void**)&qk_,     g_qk);
    cudaGetSymbolAddress((void**)&dqdkh_,  g_dqdkh);
    cudaGetSymbolAddress((void**)&P_,      g_P);
    cudaGetSymbolAddress((void**)&tmp_,    g_tmp);
    cudaGetSymbolAddress((void**)&wstack_, g_wstack);
    cudaGetSymbolAddress((void**)&wstackT_,g_wstackT);
    cudaGetSymbolAddress((void**)&enct_,   g_enct);
    cudaGetSymbolAddress((void**)&dect_,   g_dect);
    cudaGetSymbolAddress((void**)&xt_,     g_xt);

    cudaFuncSetAttribute((const void*)gemm_h_k<true,  false, false, false, false>,
                         cudaFuncAttributeMaxDynamicSharedMemorySize, SMEM_GEMM_BYTES);
    cudaFuncSetAttribute((const void*)gemm_h_k<false, false, false, false, true>,
                         cudaFuncAttributeMaxDynamicSharedMemorySize, SMEM_GEMM_BYTES);
    cudaFuncSetAttribute((const void*)gemm_h_k<false, false, true,  false, false>,
                         cudaFuncAttributeMaxDynamicSharedMemorySize, SMEM_GEMM_BYTES);
    cudaFuncSetAttribute((const void*)attn_score_softmax_k,
                         cudaFuncAttributeMaxDynamicSharedMemorySize, SS_SMEM);

    const dim3 blk(256);
    const int  mtiles = (MROWS + BM - 1) / BM;     // 25
    const dim3 gridFused(BIGK / BN, mtiles);       // (36, 25)
    const dim3 gridMega(TKN / BN, mtiles);         // (6, 25)
    const dim3 gridEnc(TKN / BN, (MENC + BM - 1) / BM);

    // one-time fp16 conversions
    cvt_h_k<<<(TKN*TKN + 255) / 256, blk>>>(wq,    wstack_,              TKN*TKN);
    cvt_h_k<<<(TKN*TKN + 255) / 256, blk>>>(wk,    wstack_ + TKN*TKN,    TKN*TKN);
    cvt_h_k<<<(HIDN*TKN + 255) / 256, blk>>>(w_hop, wstack_ + 2*TKN*TKN, HIDN*TKN);
    cvt_h_k<<<(TKN*TKN + 255) / 256, blk>>>(w_enc, enct_, TKN*TKN);
    cvt_h_k<<<(TKN*TKN + 255) / 256, blk>>>(w_dec, dect_, TKN*TKN);
    cvt_h_k<<<(MENC*TKN + 255) / 256, blk>>>(x,     xt_,   MENC*TKN);
    trans_h_k<<<dim3((TKN + 31) / 32, (BIGK + 31) / 32), dim3(32, 8)>>>(
        wstack_, wstackT_, BIGK, TKN);

    // encode + assemble
    gemm_h_k<true, false, false, false, false><<<gridEnc, blk, SMEM_GEMM_BYTES>>>(
        xt_, enct_, b_enc, tmp_, nullptr, MENC, TKN, TKN, TKN);
    assemble_t_k<<<(MROWS * TKN + 255) / 256, blk>>>(tmp_, cls, pos);

    for (int s = 0; s < KSTEPS; s++) {
        ln_kernel<<<MROWS, blk>>>(t_, eln_g, eln_b, g_, 1);
        // fused projections: [q|k] -> qk ; relu(h) -> dqdkh cols 1536+
        gemm_h_k<false, false, false, false, true><<<gridFused, blk, SMEM_GEMM_BYTES>>>(
            g_, wstack_, nullptr, qk_, dqdkh_, MROWS, BIGK, TKN, 0);
        attn_score_softmax_k<<<dim3(4, BHN), blk, SS_SMEM>>>(qk_, P_);
        attn_av_mma_k<false><<<dim3(4, BHN), dim3(128)>>>(P_, qk_, dqdkh_, TKN, 0);
        attn_av_mma_k<true ><<<dim3(4, BHN), dim3(128)>>>(P_, qk_, dqdkh_, 0, TKN);
        // mega accumulate: t += [dq|dk|relu(h)] @ wstackT^T
        gemm_h_k<false, false, true, false, false><<<gridMega, blk, SMEM_GEMM_BYTES>>>(
            dqdkh_, wstackT_, nullptr, t_, nullptr, MROWS, TKN, BIGK, TKN);
    }

    ln_kernel<<<MROWS, blk>>>(t_, dec_w, dec_b, g_, 0);
    gemm_h_k<true, false, false, false, false><<<gridMega, blk, SMEM_GEMM_BYTES>>>(
        g_, dect_, b_dec, tmp_, nullptr, MROWS, TKN, TKN, TKN);
    copy_out_k<<<(BB * NTOK * TKN + 255) / 256, blk>>>(tmp_, out);
}

// round 13
// speedup vs baseline: 1.2281x; 1.0123x over previous
#include <cuda_runtime.h>
#include <cuda_fp16.h>
#include <math.h>

// ---------------- problem constants ----------------
#define BB    32
#define NTOK  196
#define NP1   197
#define TKN   768
#define HH    12
#define ZZ    64
#define HIDN  3072
#define MROWS (BB*NP1)    // 6304
#define MENC  (BB*NTOK)   // 6272
#define BHN   (BB*HH)     // 384
#define KSTEPS 12
#define BETA_S 0.125f
#define EPS_LN 1e-5f
#define QKW   1536
#define BIGK  4608

typedef unsigned short ushort_t;

// ---------------- scratch (device globals; no allocation) ----------------
__device__ float    g_t    [MROWS*TKN];      // fp32 state
__device__ ushort_t g_g    [MROWS*TKN];      // fp16
__device__ ushort_t g_qk   [MROWS*QKW];      // fp16: q | k
__device__ ushort_t g_dqdkh[MROWS*BIGK];     // fp16: dq | dk | relu(h)
__device__ ushort_t g_P    [BHN*NP1*NP1];    // fp16 post-softmax
__device__ float    g_tmp  [MROWS*TKN];      // fp32 temp
__device__ ushort_t g_wstack [BIGK*TKN];     // fp16: [wq;wk;whop] rows
__device__ ushort_t g_wstackT[TKN*BIGK];     // fp16: transpose
__device__ ushort_t g_enct [TKN*TKN];
__device__ ushort_t g_dect [TKN*TKN];
__device__ ushort_t g_xt   [MENC*TKN];

__device__ __forceinline__ ushort_t f2h(float f) {
    return __half_as_ushort(__float2half_rn(f));
}

__device__ __forceinline__ void mma16(float c[4], const unsigned a[4], const unsigned b[2]) {
    asm volatile(
        "mma.sync.aligned.m16n8k16.row.col.f32.f16.f16.f32 "
        "{%0,%1,%2,%3}, {%4,%5,%6,%7}, {%8,%9}, {%0,%1,%2,%3};\n"
        : "+f"(c[0]), "+f"(c[1]), "+f"(c[2]), "+f"(c[3])
        : "r"(a[0]), "r"(a[1]), "r"(a[2]), "r"(a[3]), "r"(b[0]), "r"(b[1]));
}

__global__ void cvt_h_k(const float* __restrict__ in, ushort_t* __restrict__ out, int n)
{
    int i = blockIdx.x * 256 + threadIdx.x;
    if (i < n) out[i] = f2h(in[i]);
}

// tiled half transpose: out[Cc x R] = in[R x Cc]^T
__global__ void trans_h_k(const ushort_t* __restrict__ in, ushort_t* __restrict__ out,
                          int R, int Cc)
{
    __shared__ ushort_t tile[32][33];
    int c0 = blockIdx.x * 32, r0 = blockIdx.y * 32;
    int x = threadIdx.x, y = threadIdx.y;
#pragma unroll
    for (int j = 0; j < 32; j += 8) {
        int r = r0 + y + j, c = c0 + x;
        tile[y + j][x] = (r < R && c < Cc) ? in[(size_t)r * Cc + c] : (ushort_t)0;
    }
    __syncthreads();
#pragma unroll
    for (int j = 0; j < 32; j += 8) {
        int r = c0 + y + j, c = r0 + x;
        if (r < Cc && c < R) out[(size_t)r * R + c] = tile[x][y + j];
    }
}

// ============ fp16 GEMM (NT): BM=256 BN=128 BK=64, 256 thr, warp 64x64 ============
#define STAGES 3
#define BM 256
#define BN 128
#define BKH 64
#define AS_H 72
#define A_STG_H (BM*AS_H)
#define B_STG_H (128*AS_H)
#define SMEM_GEMM_BYTES (STAGES*(A_STG_H+B_STG_H)*2)   // 165888

__device__ __forceinline__ void cp16(unsigned dst, const void* src, int sz) {
    asm volatile("cp.async.cg.shared.global [%0], [%1], 16, %2;\n"
                 :: "r"(dst), "l"(src), "r"(sz));
}
__device__ __forceinline__ void cp_commit() { asm volatile("cp.async.commit_group;\n"); }
__device__ __forceinline__ void cp_wait1()  { asm volatile("cp.async.wait_group 1;\n"); }

__device__ __forceinline__ void load_stage_h(
    const ushort_t* __restrict__ A, const ushort_t* __restrict__ B,
    int M, int K, int m0, int n0, int kt, int tid,
    unsigned sA, unsigned sB)
{
#pragma unroll
    for (int s = 0; s < 8; s++) {
        int id = tid + s * 256;
        int r = id >> 3, c8 = (id & 7) << 3;
        unsigned dst = sA + (unsigned)(r * AS_H + c8) * 2u;
        bool ok = (m0 + r < M);
        const ushort_t* src = ok ? (A + (size_t)(m0 + r) * K + kt + c8) : A;
        cp16(dst, src, ok ? 16 : 0);
    }
#pragma unroll
    for (int s = 0; s < 4; s++) {
        int id = tid + s * 256;
        int r = id >> 3, c8 = (id & 7) << 3;
        unsigned dst = sB + (unsigned)(r * AS_H + c8) * 2u;
        cp16(dst, B + (size_t)(n0 + r) * K + kt + c8, 16);
    }
}

// SPLIT: cols < QKW -> fp16 Cv (ldc QKW); cols >= QKW -> relu fp16 Cv2 (ldc BIGK)
template<bool BIAS, bool RELU, bool ACC, bool OTF, bool SPLIT>
__global__ void __launch_bounds__(256, 1) gemm_h_k(
    const ushort_t* __restrict__ A, const ushort_t* __restrict__ B,
    const float* __restrict__ bias, void* __restrict__ Cv, void* __restrict__ Cv2,
    int M, int N, int K, int ldc)
{
    extern __shared__ ushort_t smh[];
    const int tid = threadIdx.x;
    const int m0 = blockIdx.y * BM, n0 = blockIdx.x * BN;
    const int lane = tid & 31, wid = tid >> 5;
    const int wm = (wid & 3) * 64, wn = (wid >> 2) * 64;
    const int g = lane >> 2, tig = lane & 3;

    unsigned smem_u = (unsigned)__cvta_generic_to_shared(smh);
    unsigned sB_base = smem_u + (unsigned)(STAGES * A_STG_H) * 2u;

    float acc[4][8][4];
#pragma unroll
    for (int mi = 0; mi < 4; mi++)
#pragma unroll
        for (int ni = 0; ni < 8; ni++)
#pragma unroll
            for (int v = 0; v < 4; v++) acc[mi][ni][v] = 0.f;

    const int niter = K >> 6;

#pragma unroll
    for (int p = 0; p < STAGES - 1; p++) {
        load_stage_h(A, B, M, K, m0, n0, p * BKH, tid,
                     smem_u + (unsigned)(p * A_STG_H) * 2u,
                     sB_base + (unsigned)(p * B_STG_H) * 2u);
        cp_commit();
    }

    int stc = 0;
    for (int it = 0; it < niter; it++) {
        cp_wait1();
        __syncthreads();

        int pf = it + STAGES - 1;
        if (pf < niter) {
            int st = pf % STAGES;
            load_stage_h(A, B, M, K, m0, n0, pf * BKH, tid,
                         smem_u + (unsigned)(st * A_STG_H) * 2u,
                         sB_base + (unsigned)(st * B_STG_H) * 2u);
        }
        cp_commit();

        const unsigned* Aw = (const unsigned*)(smh + stc * A_STG_H);
        const unsigned* Bw = (const unsigned*)(smh + STAGES * A_STG_H + stc * B_STG_H);
        stc = (stc + 1 == STAGES) ? 0 : stc + 1;
#pragma unroll
        for (int ks = 0; ks < 4; ks++) {
            unsigned af[4][4], bf[8][2];
#pragma unroll
            for (int mi = 0; mi < 4; mi++) {
                const unsigned* p0 = Aw + (wm + mi * 16 + g) * 36 + ks * 8 + tig;
                af[mi][0] = p0[0];
                af[mi][1] = p0[8 * 36];
                af[mi][2] = p0[4];
                af[mi][3] = p0[8 * 36 + 4];
            }
#pragma unroll
            for (int ni = 0; ni < 8; ni++) {
                const unsigned* p = Bw + (wn + ni * 8 + g) * 36 + ks * 8 + tig;
                bf[ni][0] = p[0];
                bf[ni][1] = p[4];
            }
#pragma unroll
            for (int mi = 0; mi < 4; mi++)
#pragma unroll
                for (int ni = 0; ni < 8; ni++)
                    mma16(acc[mi][ni], af[mi], bf[ni]);
        }
    }

#pragma unroll
    for (int mi = 0; mi < 4; mi++) {
#pragma unroll
        for (int half = 0; half < 2; half++) {
            int row = m0 + wm + mi * 16 + g + half * 8;
            if (row < M) {
#pragma unroll
                for (int ni = 0; ni < 8; ni++) {
                    int col = n0 + wn + ni * 8 + tig * 2;
                    float v0 = acc[mi][ni][half * 2 + 0];
                    float v1 = acc[mi][ni][half * 2 + 1];
                    if (SPLIT) {
                        if (n0 < QKW) {
                            ushort_t* crow = (ushort_t*)Cv + (size_t)row * QKW;
                            crow[col] = f2h(v0); crow[col + 1] = f2h(v1);
                        } else {
                            ushort_t* crow = (ushort_t*)Cv2 + (size_t)row * BIGK;
                            crow[col] = f2h(fmaxf(v0, 0.f));
                            crow[col + 1] = f2h(fmaxf(v1, 0.f));
                        }
                    } else {
                        if (BIAS) { v0 += bias[col]; v1 += bias[col + 1]; }
                        if (RELU) { v0 = fmaxf(v0, 0.f); v1 = fmaxf(v1, 0.f); }
                        if (OTF) {
                            ushort_t* crow = (ushort_t*)Cv + (size_t)row * ldc;
                            crow[col] = f2h(v0); crow[col + 1] = f2h(v1);
                        } else {
                            float* crow = (float*)Cv + (size_t)row * ldc;
                            if (ACC) { v0 += crow[col]; v1 += crow[col + 1]; }
                            crow[col] = v0; crow[col + 1] = v1;
                        }
                    }
                }
            }
        }
    }
}

// ---------------- LayerNorm (writes fp16) ----------------
__device__ __forceinline__ float block_sum_256(float v, float* red)
{
    int lane = threadIdx.x & 31, w = threadIdx.x >> 5;
#pragma unroll
    for (int o = 16; o; o >>= 1) v += __shfl_xor_sync(0xffffffffu, v, o);
    if (lane == 0) red[w] = v;
    __syncthreads();
    if (w == 0) {
        float r = (lane < 8) ? red[lane] : 0.f;
#pragma unroll
        for (int o = 4; o; o >>= 1) r += __shfl_xor_sync(0xffffffffu, r, o);
        if (lane == 0) red[0] = r;
    }
    __syncthreads();
    float out = red[0];
    __syncthreads();
    return out;
}

__global__ void __launch_bounds__(256) ln_kernel(
    const float* __restrict__ X, const float* __restrict__ w,
    const float* __restrict__ bvec, ushort_t* __restrict__ Y, int scalar_w)
{
    __shared__ float red[32];
    int row = blockIdx.x;
    const float* x = X + (size_t)row * TKN;
    ushort_t* y = Y + (size_t)row * TKN;
    int tid = threadIdx.x;
    float v[3];
    float s = 0.f, ss = 0.f;
#pragma unroll
    for (int i = 0; i < 3; i++) {
        float t = x[tid + i * 256];
        v[i] = t; s += t; ss += t * t;
    }
    float sum  = block_sum_256(s, red);
    float sum2 = block_sum_256(ss, red);
    float mu = sum * (1.f / TKN);
    float var = sum2 * (1.f / TKN) - mu * mu;
    float r = rsqrtf(var + EPS_LN);
#pragma unroll
    for (int i = 0; i < 3; i++) {
        int c = tid + i * 256;
        float gv = (v[i] - mu) * r;
        float wv = scalar_w ? w[0] : w[c];
        y[c] = f2h(gv * wv + bvec[c]);
    }
}

// ---------------- assemble t = [cls ; enc] + pos ----------------
__global__ void assemble_t_k(const float* __restrict__ enc,
                             const float* __restrict__ cls,
                             const float* __restrict__ pos)
{
    int idx = blockIdx.x * 256 + threadIdx.x;
    if (idx >= MROWS * TKN) return;
    int d = idx % TKN;
    int row = idx / TKN;
    int b = row / NP1, n = row % NP1;
    float v;
    if (n == 0) v = cls[d];
    else        v = enc[((size_t)(b * NTOK + n - 1)) * TKN + d];
    g_t[idx] = v + pos[n * TKN + d];
}

// ---------------- fused scores + softmax + dq (dq = P @ K) ----------------
// grid (4 qtiles, BHN), 256 threads.
// smem: Qs 64x72h (reused as K^T in dq phase) + Ks 64x72h + Sc 64x264 f32
// After softmax, Sc region is reused as fp16 P staging [64][264].
#define SC_STRIDE 264
#define PH_STRIDE 264
#define SS_SMEM (2*64*AS_H*2 + 64*SC_STRIDE*4)   // 86016
__global__ void __launch_bounds__(256) attn_score_softmax_dq_k(
    const ushort_t* __restrict__ QK, ushort_t* __restrict__ P,
    ushort_t* __restrict__ OutB)
{
    extern __shared__ ushort_t ssm[];
    ushort_t* Qs = ssm;
    ushort_t* Ks = ssm + 64 * AS_H;
    float*    Sc = (float*)(ssm + 2 * 64 * AS_H);

    int bh = blockIdx.y, b = bh / HH, h = bh % HH;
    int q0 = blockIdx.x * 64;
    const ushort_t* Qb = QK + (size_t)b * NP1 * QKW + h * ZZ;
    const ushort_t* Kb = Qb + TKN;
    int tid = threadIdx.x;
    int lane = tid & 31, wid = tid >> 5;
    int wm = (wid & 3) * 16, wn = (wid >> 2) * 32;
    int g = lane >> 2, tig = lane & 3;

#pragma unroll
    for (int s = 0; s < 2; s++) {
        int id = tid + s * 256;
        int r = id >> 3, c8 = (id & 7) << 3;
        uint4 qv = (q0 + r < NP1) ? *(const uint4*)(Qb + (size_t)(q0 + r) * QKW + c8)
                                  : make_uint4(0u, 0u, 0u, 0u);
        *(uint4*)&Qs[r * AS_H + c8] = qv;
    }

    for (int kt = 0; kt < 4; kt++) {
        int k0 = kt * 64;
        __syncthreads();
#pragma unroll
        for (int s = 0; s < 2; s++) {
            int id = tid + s * 256;
            int r = id >> 3, c8 = (id & 7) << 3;
            uint4 kv = (k0 + r < NP1) ? *(const uint4*)(Kb + (size_t)(k0 + r) * QKW + c8)
                                      : make_uint4(0u, 0u, 0u, 0u);
            *(uint4*)&Ks[r * AS_H + c8] = kv;
        }
        __syncthreads();

        const unsigned* Qw = (const unsigned*)Qs;
        const unsigned* Kw = (const unsigned*)Ks;
        float acc[4][4];
#pragma unroll
        for (int ni = 0; ni < 4; ni++)
#pragma unroll
            for (int v = 0; v < 4; v++) acc[ni][v] = 0.f;
#pragma unroll
        for (int ks = 0; ks < 4; ks++) {
            unsigned af[4], bf[4][2];
            const unsigned* pa = Qw + (wm + g) * 36 + ks * 8 + tig;
            af[0] = pa[0]; af[1] = pa[8 * 36]; af[2] = pa[4]; af[3] = pa[8 * 36 + 4];
#pragma unroll
            for (int ni = 0; ni < 4; ni++) {
                const unsigned* pb = Kw + (wn + ni * 8 + g) * 36 + ks * 8 + tig;
                bf[ni][0] = pb[0]; bf[ni][1] = pb[4];
            }
#pragma unroll
            for (int ni = 0; ni < 4; ni++)
                mma16(acc[ni], af, bf[ni]);
        }
#pragma unroll
        for (int half = 0; half < 2; half++) {
            int row = wm + g + half * 8;
#pragma unroll
            for (int ni = 0; ni < 4; ni++) {
                int col = k0 + wn + ni * 8 + tig * 2;
                Sc[row * SC_STRIDE + col]     = acc[ni][half * 2 + 0];
                Sc[row * SC_STRIDE + col + 1] = acc[ni][half * 2 + 1];
            }
        }
    }
    __syncthreads();

    // softmax: warp wid handles rows wid*8..wid*8+7.
    // Writes fp16 P to gmem AND re-stages fp16 P into the Sc region (Ph).
    ushort_t* Ph = (ushort_t*)Sc;
    ushort_t* Pp = P + (size_t)bh * NP1 * NP1;
#pragma unroll
    for (int rr = 0; rr < 8; rr++) {
        int row = wid * 8 + rr;
        int grow = q0 + row;
        float vals[7];
        float m = -1e30f;
        if (grow < NP1) {
#pragma unroll
            for (int i = 0; i < 7; i++) {
                int c = lane + i * 32;
                float v = (c < NP1) ? BETA_S * Sc[row * SC_STRIDE + c] : -1e30f;
                vals[i] = v;
                m = fmaxf(m, v);
            }
#pragma unroll
            for (int o = 16; o; o >>= 1) m = fmaxf(m, __shfl_xor_sync(0xffffffffu, m, o));
            float s = 0.f;
#pragma unroll
            for (int i = 0; i < 7; i++) {
                int c = lane + i * 32;
                float e = (c < NP1) ? __expf(vals[i] - m) : 0.f;
                vals[i] = e; s += e;
            }
#pragma unroll
            for (int o = 16; o; o >>= 1) s += __shfl_xor_sync(0xffffffffu, s, o);
            float inv = 1.f / s;
            ushort_t* prow = Pp + (size_t)grow * NP1;
#pragma unroll
            for (int i = 0; i < 8; i++) {
                int c = lane + i * 32;
                ushort_t hv = 0;
                if (i < 7 && c < NP1) {
                    hv = f2h(vals[i] * inv);
                    prow[c] = hv;
                }
                Ph[row * PH_STRIDE + c] = hv;
            }
        } else {
            // zero the staged row so dq mma reads clean data (results discarded anyway)
#pragma unroll
            for (int i = 0; i < 8; i++) {
                int c = lane + i * 32;
                Ph[row * PH_STRIDE + c] = 0;
            }
        }
    }
    __syncthreads();

    // dq phase: dq[q, z] = sum_k P[q,k] * K[k,z]  (64 rows x 64 z, K=256 padded)
    ushort_t* Kt = Qs;   // reuse Q buffer: K^T staging [z][key], stride AS_H
    float dacc[4][4];
#pragma unroll
    for (int ni = 0; ni < 4; ni++)
#pragma unroll
        for (int v = 0; v < 4; v++) dacc[ni][v] = 0.f;

    for (int kt = 0; kt < 4; kt++) {
        int k0 = kt * 64;
        __syncthreads();
        // stage K^T: Kt[z][r] = K[k0+r][z]
#pragma unroll
        for (int s = 0; s < 2; s++) {
            int id = tid + s * 256;
            int r = id >> 3, c8 = (id & 7) << 3;
            uint4 v = (k0 + r < NP1) ? *(const uint4*)(Kb + (size_t)(k0 + r) * QKW + c8)
                                     : make_uint4(0u, 0u, 0u, 0u);
            ushort_t hv[8];
            *(uint4*)hv = v;
#pragma unroll
            for (int j = 0; j < 8; j++) Kt[(c8 + j) * AS_H + r] = hv[j];
        }
        __syncthreads();

        const unsigned* Pw = (const unsigned*)Ph;
        const unsigned* Kw = (const unsigned*)Kt;
#pragma unroll
        for (int ks = 0; ks < 4; ks++) {
            unsigned af[4], bf[4][2];
            const unsigned* pa = Pw + (wm + g) * (PH_STRIDE / 2) + kt * 32 + ks * 8 + tig;
            af[0] = pa[0];
            af[1] = pa[8 * (PH_STRIDE / 2)];
            af[2] = pa[4];
            af[3] = pa[8 * (PH_STRIDE / 2) + 4];
#pragma unroll
            for (int ni = 0; ni < 4; ni++) {
                const unsigned* pb = Kw + (wn + ni * 8 + g) * 36 + ks * 8 + tig;
                bf[ni][0] = pb[0]; bf[ni][1] = pb[4];
            }
#pragma unroll
            for (int ni = 0; ni < 4; ni++)
                mma16(dacc[ni], af, bf[ni]);
        }
    }

    // write dq to dqdkh cols [h*64, h*64+64)
    ushort_t* Ob = OutB + (size_t)b * NP1 * BIGK + h * ZZ;
#pragma unroll
    for (int half = 0; half < 2; half++) {
        int grow = q0 + wm + g + half * 8;
        if (grow < NP1) {
            ushort_t* orow = Ob + (size_t)grow * BIGK;
#pragma unroll
            for (int ni = 0; ni < 4; ni++) {
                int col = wn + ni * 8 + tig * 2;
                orow[col]     = f2h(dacc[ni][half * 2 + 0]);
                orow[col + 1] = f2h(dacc[ni][half * 2 + 1]);
            }
        }
    }
}

// ---------------- attention dk via fp16 mma: dk = P^T @ Q ----------------
__global__ void __launch_bounds__(128) attn_av_mma_k(
    const ushort_t* __restrict__ Pb, const ushort_t* __restrict__ QK,
    ushort_t* __restrict__ OutB, int v_off, int o_off)
{
    __shared__ ushort_t Ps[64 * 40];
    __shared__ ushort_t Vt[64 * 40];
    int bh = blockIdx.y, b = bh / HH, h = bh % HH;
    const ushort_t* Pp = Pb + (size_t)bh * NP1 * NP1;
    const ushort_t* Vb = QK + (size_t)b * NP1 * QKW + v_off + h * ZZ;
    ushort_t* Ob = OutB + (size_t)b * NP1 * BIGK + o_off + h * ZZ;
    int m0 = blockIdx.x * 64;
    int tid = threadIdx.x, lane = tid & 31, wid = tid >> 5;
    int g = lane >> 2, tig = lane & 3, wm = wid * 16;
    float acc[8][4];
#pragma unroll
    for (int ni = 0; ni < 8; ni++)
#pragma unroll
        for (int v = 0; v < 4; v++) acc[ni][v] = 0.f;

    for (int kb = 0; kb < NP1; kb += 32) {
        __syncthreads();
        // stage P^T chunk [64 m][32 k]
#pragma unroll
        for (int s = 0; s < 16; s++) {
            int id = tid + s * 128;
            int r = id & 63, kk = id >> 6;
            ushort_t v = 0;
            int mg = m0 + r, kg = kb + kk;
            if (mg < NP1 && kg < NP1)
                v = Pp[(size_t)kg * NP1 + mg];
            Ps[r * 40 + kk] = v;
        }
#pragma unroll
        for (int s = 0; s < 2; s++) {
            int id = tid + s * 128;
            int r = id >> 3, c8 = (id & 7) << 3;
            uint4 v = (kb + r < NP1) ? *(const uint4*)(Vb + (size_t)(kb + r) * QKW + c8)
                                     : make_uint4(0u, 0u, 0u, 0u);
            ushort_t hv[8];
            *(uint4*)hv = v;
#pragma unroll
            for (int j = 0; j < 8; j++) Vt[(c8 + j) * 40 + r] = hv[j];
        }
        __syncthreads();
        const unsigned* Pw = (const unsigned*)Ps;
        const unsigned* Vw = (const unsigned*)Vt;
#pragma unroll
        for (int ks = 0; ks < 2; ks++) {
            unsigned af[4], bf[8][2];
            const unsigned* pa = Pw + (wm + g) * 20 + ks * 8 + tig;
            af[0] = pa[0]; af[1] = pa[8 * 20]; af[2] = pa[4]; af[3] = pa[8 * 20 + 4];
#pragma unroll
            for (int ni = 0; ni < 8; ni++) {
                const unsigned* pb = Vw + (ni * 8 + g) * 20 + ks * 8 + tig;
                bf[ni][0] = pb[0]; bf[ni][1] = pb[4];
            }
#pragma unroll
            for (int ni = 0; ni < 8; ni++)
                mma16(acc[ni], af, bf[ni]);
        }
    }
#pragma unroll
    for (int half = 0; half < 2; half++) {
        int row = m0 + wm + g + half * 8;
        if (row < NP1) {
            ushort_t* orow = Ob + (size_t)row * BIGK;
#pragma unroll
            for (int ni = 0; ni < 8; ni++) {
                int col = ni * 8 + tig * 2;
                orow[col]     = f2h(acc[ni][half * 2]);
                orow[col + 1] = f2h(acc[ni][half * 2 + 1]);
            }
        }
    }
}

// ---------------- final copy (drop cls row) ----------------
__global__ void copy_out_k(const float* __restrict__ Y, float* __restrict__ out)
{
    int idx = blockIdx.x * 256 + threadIdx.x;
    if (idx >= BB * NTOK * TKN) return;
    int d = idx % TKN;
    int r = idx / TKN;
    int b = r / NTOK, j = r % NTOK;
    out[idx] = Y[((size_t)(b * NP1 + j + 1)) * TKN + d];
}

// ---------------- driver ----------------
extern "C" void kernel_launch(void* const* d_in, const int* in_sizes, int n_in,
                              void* d_out, int out_size)
{
    const float* x      = (const float*)d_in[0];
    const float* w_enc  = (const float*)d_in[1];
    const float* b_enc  = (const float*)d_in[2];
    const float* cls    = (const float*)d_in[3];
    const float* pos    = (const float*)d_in[4];
    const float* eln_g  = (const float*)d_in[5];
    const float* eln_b  = (const float*)d_in[6];
    const float* wq     = (const float*)d_in[7];
    const float* wk     = (const float*)d_in[8];
    const float* w_hop  = (const float*)d_in[9];
    const float* dec_w  = (const float*)d_in[10];
    const float* dec_b  = (const float*)d_in[11];
    const float* w_dec  = (const float*)d_in[12];
    const float* b_dec  = (const float*)d_in[13];
    float* out = (float*)d_out;

    float *t_, *tmp_;
    ushort_t *g_, *qk_, *dqdkh_, *P_, *wstack_, *wstackT_, *enct_, *dect_, *xt_;
    cudaGetSymbolAddress((void**)&t_,      g_t);
    cudaGetSymbolAddress((void**)&g_,      g_g);
    cudaGetSymbolAddress((void**)&qk_,     g_qk);
    cudaGetSymbolAddress((void**)&dqdkh_,  g_dqdkh);
    cudaGetSymbolAddress((void**)&P_,      g_P);
    cudaGetSymbolAddress((void**)&tmp_,    g_tmp);
    cudaGetSymbolAddress((void**)&wstack_, g_wstack);
    cudaGetSymbolAddress((void**)&wstackT_,g_wstackT);
    cudaGetSymbolAddress((void**)&enct_,   g_enct);
    cudaGetSymbolAddress((void**)&dect_,   g_dect);
    cudaGetSymbolAddress((void**)&xt_,     g_xt);

    cudaFuncSetAttribute((const void*)gemm_h_k<true,  false, false, false, false>,
                         cudaFuncAttributeMaxDynamicSharedMemorySize, SMEM_GEMM_BYTES);
    cudaFuncSetAttribute((const void*)gemm_h_k<false, false, false, false, true>,
                         cudaFuncAttributeMaxDynamicSharedMemorySize, SMEM_GEMM_BYTES);
    cudaFuncSetAttribute((const void*)gemm_h_k<false, false, true,  false, false>,
                         cudaFuncAttributeMaxDynamicSharedMemorySize, SMEM_GEMM_BYTES);
    cudaFuncSetAttribute((const void*)attn_score_softmax_dq_k,
                         cudaFuncAttributeMaxDynamicSharedMemorySize, SS_SMEM);

    const dim3 blk(256);
    const int  mtiles = (MROWS + BM - 1) / BM;     // 25
    const dim3 gridFused(BIGK / BN, mtiles);       // (36, 25)
    const dim3 gridMega(TKN / BN, mtiles);         // (6, 25)
    const dim3 gridEnc(TKN / BN, (MENC + BM - 1) / BM);

    // one-time fp16 conversions
    cvt_h_k<<<(TKN*TKN + 255) / 256, blk>>>(wq,    wstack_,              TKN*TKN);
    cvt_h_k<<<(TKN*TKN + 255) / 256, blk>>>(wk,    wstack_ + TKN*TKN,    TKN*TKN);
    cvt_h_k<<<(HIDN*TKN + 255) / 256, blk>>>(w_hop, wstack_ + 2*TKN*TKN, HIDN*TKN);
    cvt_h_k<<<(TKN*TKN + 255) / 256, blk>>>(w_enc, enct_, TKN*TKN);
    cvt_h_k<<<(TKN*TKN + 255) / 256, blk>>>(w_dec, dect_, TKN*TKN);
    cvt_h_k<<<(MENC*TKN + 255) / 256, blk>>>(x,     xt_,   MENC*TKN);
    trans_h_k<<<dim3((TKN + 31) / 32, (BIGK + 31) / 32), dim3(32, 8)>>>(
        wstack_, wstackT_, BIGK, TKN);

    // encode + assemble
    gemm_h_k<true, false, false, false, false><<<gridEnc, blk, SMEM_GEMM_BYTES>>>(
        xt_, enct_, b_enc, tmp_, nullptr, MENC, TKN, TKN, TKN);
    assemble_t_k<<<(MROWS * TKN + 255) / 256, blk>>>(tmp_, cls, pos);

    for (int s = 0; s < KSTEPS; s++) {
        ln_kernel<<<MROWS, blk>>>(t_, eln_g, eln_b, g_, 1);
        // fused projections: [q|k] -> qk ; relu(h) -> dqdkh cols 1536+
        gemm_h_k<false, false, false, false, true><<<gridFused, blk, SMEM_GEMM_BYTES>>>(
            g_, wstack_, nullptr, qk_, dqdkh_, MROWS, BIGK, TKN, 0);
        // scores + softmax + dq (writes P and dqdkh cols 0..767)
        attn_score_softmax_dq_k<<<dim3(4, BHN), blk, SS_SMEM>>>(qk_, P_, dqdkh_);
        // dk = P^T @ Q -> dqdkh cols 768..1535
        attn_av_mma_k<<<dim3(4, BHN), dim3(128)>>>(P_, qk_, dqdkh_, 0, TKN);
        // mega accumulate: t += [dq|dk|relu(h)] @ wstackT^T
        gemm_h_k<false, false, true, false, false><<<gridMega, blk, SMEM_GEMM_BYTES>>>(
            dqdkh_, wstackT_, nullptr, t_, nullptr, MROWS, TKN, BIGK, TKN);
    }

    ln_kernel<<<MROWS, blk>>>(t_, dec_w, dec_b, g_, 0);
    gemm_h_k<true, false, false, false, false><<<gridMega, blk, SMEM_GEMM_BYTES>>>(
        g_, dect_, b_dec, tmp_, nullptr, MROWS, TKN, TKN, TKN);
    copy_out_k<<<(BB * NTOK * TKN + 255) / 256, blk>>>(tmp_, out);
}